// round 1
// baseline (speedup 1.0000x reference)
#include <cuda_runtime.h>
#include <cstdint>

#define NB_B 8192
#define LOD 60
#define LSD 120
#define AD 10
#define NB 15
#define HH 60
#define BT 32      // batch elements per block (== warp width)
#define YD 20      // blockDim.y (row groups)
#define RPT 3      // rows per thread (YD*RPT == LOD)
#define NT (BT*YD)
#define PAD 33     // per-batch smem stride (conflict-free)

// band-extracted transition tensors: [i][jj][k] -> (tm11,tm12,tm21,tm22)
__device__ float4 g_tmb[LOD * 7 * NB];

__global__ void pack_tmb_kernel(const float* __restrict__ tm11,
                                const float* __restrict__ tm12,
                                const float* __restrict__ tm21,
                                const float* __restrict__ tm22) {
    int idx = blockIdx.x * blockDim.x + threadIdx.x;
    if (idx >= LOD * 7 * NB) return;
    int k = idx % NB;
    int jj = (idx / NB) % 7;
    int i = idx / (NB * 7);
    int j = i + jj - 3;
    float4 v = make_float4(0.f, 0.f, 0.f, 0.f);
    if (j >= 0 && j < LOD) {
        int off = k * LOD * LOD + i * LOD + j;
        v.x = tm11[off]; v.y = tm12[off]; v.z = tm21[off]; v.w = tm22[off];
    }
    g_tmb[idx] = v;
}

// ---- smem layout (float offsets) ----
#define OFF_TMB   0            // 25200 (float4[6300])
#define OFF_IN    25200        // 5 * 60*33 = 9900 (mu,ml,cu,cl,cs) ; reused as out[300*33]
#define OFF_WC2P  35100        // float2[60*60] = 7200 floats
#define OFF_COEF  42300        // 15*33
#define OFF_ACT   42795        // 10*33
#define OFF_H     43125        // 60*33
#define OFF_WCOEF 45105        // 15*120
#define OFF_WC1   46905        // 60*10
#define OFF_BC1   47505        // 60
#define OFF_BC2   47565        // 120
#define OFF_BCOEF 47685        // 15
#define OFF_TC    47700        // 120
#define SMEM_FLOATS 47820

__global__ void __launch_bounds__(NT, 1) acpredict_kernel(
    const float* __restrict__ post_mean, const float* __restrict__ cu_g,
    const float* __restrict__ cl_g, const float* __restrict__ cs_g,
    const float* __restrict__ action, const float* __restrict__ log_noise,
    const float* __restrict__ w_coef, const float* __restrict__ b_coef,
    const float* __restrict__ w_c1, const float* __restrict__ b_c1,
    const float* __restrict__ w_c2, const float* __restrict__ b_c2,
    float* __restrict__ out)
{
    extern __shared__ float sm[];
    float*  s_tmb   = sm + OFF_TMB;
    float*  s_mu    = sm + OFF_IN;
    float*  s_ml    = s_mu + LOD * PAD;
    float*  s_cu    = s_ml + LOD * PAD;
    float*  s_cl    = s_cu + LOD * PAD;
    float*  s_cs    = s_cl + LOD * PAD;
    float2* s_wc2p  = (float2*)(sm + OFF_WC2P);
    float*  s_coef  = sm + OFF_COEF;
    float*  s_act   = sm + OFF_ACT;
    float*  s_h     = sm + OFF_H;
    float*  s_wcoef = sm + OFF_WCOEF;
    float*  s_wc1   = sm + OFF_WC1;
    float*  s_bc1   = sm + OFF_BC1;
    float*  s_bc2   = sm + OFF_BC2;
    float*  s_bcoef = sm + OFF_BCOEF;
    float*  s_tc    = sm + OFF_TC;

    const int lane = threadIdx.x;
    const int y    = threadIdx.y;
    const int tid  = y * BT + lane;
    const int b0   = blockIdx.x * BT;

    // ---- load phase ----
    {
        float4* tmb4 = (float4*)s_tmb;
        for (int e = tid; e < LOD * 7 * NB; e += NT) tmb4[e] = g_tmb[e];
    }
    for (int e = tid; e < BT * LSD; e += NT) {
        int bl = e / LSD, d = e % LSD;
        float v = post_mean[(b0 + bl) * LSD + d];
        if (d < LOD) s_mu[d * PAD + bl] = v;
        else         s_ml[(d - LOD) * PAD + bl] = v;
    }
    for (int e = tid; e < BT * LOD; e += NT) {
        int bl = e / LOD, j = e % LOD;
        s_cu[j * PAD + bl] = cu_g[(b0 + bl) * LOD + j];
        s_cl[j * PAD + bl] = cl_g[(b0 + bl) * LOD + j];
        s_cs[j * PAD + bl] = cs_g[(b0 + bl) * LOD + j];
    }
    for (int e = tid; e < BT * AD; e += NT) {
        int bl = e / AD, d = e % AD;
        s_act[d * PAD + bl] = action[(b0 + bl) * AD + d];
    }
    for (int e = tid; e < NB * LSD; e += NT)  s_wcoef[e] = w_coef[e];
    for (int e = tid; e < HH * AD; e += NT)   s_wc1[e] = w_c1[e];
    for (int e = tid; e < HH; e += NT)        s_bc1[e] = b_c1[e];
    for (int e = tid; e < LSD; e += NT)       s_bc2[e] = b_c2[e];
    for (int e = tid; e < NB; e += NT)        s_bcoef[e] = b_coef[e];
    for (int e = tid; e < LSD; e += NT) {
        float x = log_noise[e];
        s_tc[e] = (x < 0.f) ? expf(x) : x + 1.f;     // elup1
    }
    for (int e = tid; e < LOD * HH; e += NT) {
        int i = e / HH, m = e % HH;
        s_wc2p[e] = make_float2(w_c2[i * HH + m], w_c2[(LOD + i) * HH + m]);
    }
    __syncthreads();

    // ---- logits (y<15) and control hidden layer ----
    if (y < NB) {
        const int k = y;
        float lg = s_bcoef[k];
        #pragma unroll 4
        for (int d = 0; d < LSD; d++) {
            float pv = (d < LOD) ? s_mu[d * PAD + lane] : s_ml[(d - LOD) * PAD + lane];
            lg = fmaf(s_wcoef[k * LSD + d], pv, lg);
        }
        s_coef[k * PAD + lane] = lg;
    }
    #pragma unroll
    for (int r = 0; r < RPT; r++) {
        int i = y + YD * r;
        float hv = s_bc1[i];
        #pragma unroll
        for (int d = 0; d < AD; d++)
            hv = fmaf(s_wc1[i * AD + d], s_act[d * PAD + lane], hv);
        s_h[i * PAD + lane] = fmaxf(hv, 0.f);
    }
    __syncthreads();

    // ---- softmax (warp 0, one batch per lane) ----
    if (y == 0) {
        float mx = -1e30f;
        #pragma unroll
        for (int k = 0; k < NB; k++) mx = fmaxf(mx, s_coef[k * PAD + lane]);
        float ex[NB], sum = 0.f;
        #pragma unroll
        for (int k = 0; k < NB; k++) { ex[k] = __expf(s_coef[k * PAD + lane] - mx); sum += ex[k]; }
        float inv = 1.f / sum;
        #pragma unroll
        for (int k = 0; k < NB; k++) s_coef[k * PAD + lane] = ex[k] * inv;
    }
    __syncthreads();

    // ---- pack coef into f32x2 (same value both halves) ----
    unsigned long long coef2[NB];
    #pragma unroll
    for (int k = 0; k < NB; k++) {
        float c = s_coef[k * PAD + lane];
        asm("mov.b64 %0, {%1, %1};" : "=l"(coef2[k]) : "f"(c));
    }

    const uint32_t tmb_base = (uint32_t)__cvta_generic_to_shared(s_tmb);

    float r_nmu[RPT], r_nml[RPT], r_ncu[RPT], r_ncl[RPT], r_ncs[RPT];

    #pragma unroll
    for (int r = 0; r < RPT; r++) {
        const int i = y + YD * r;
        float nmu = 0.f, nml = 0.f, ncu = 0.f, ncl = 0.f, ncs = 0.f;
        #pragma unroll
        for (int jj = 0; jj < 7; jj++) {
            int j  = i + jj - 3;
            int jc = min(max(j, 0), LOD - 1);       // out-of-band tm entries are 0
            float mu_j = s_mu[jc * PAD + lane];
            float ml_j = s_ml[jc * PAD + lane];
            float cuj  = s_cu[jc * PAD + lane];
            float clj  = s_cl[jc * PAD + lane];
            float csj  = s_cs[jc * PAD + lane];

            unsigned long long a01 = 0ull, a23 = 0ull;   // (t11,t12) , (t21,t22)
            uint32_t ta = tmb_base + (uint32_t)(((i * 7 + jj) * NB) * 16);
            #pragma unroll
            for (int k = 0; k < NB; k++) {
                unsigned long long v01, v23;
                asm("ld.shared.v2.u64 {%0,%1}, [%2];"
                    : "=l"(v01), "=l"(v23) : "r"(ta + (uint32_t)(k * 16)));
                asm("fma.rn.f32x2 %0, %1, %2, %0;" : "+l"(a01) : "l"(coef2[k]), "l"(v01));
                asm("fma.rn.f32x2 %0, %1, %2, %0;" : "+l"(a23) : "l"(coef2[k]), "l"(v23));
            }
            float t11, t12, t21, t22;
            asm("mov.b64 {%0,%1}, %2;" : "=f"(t11), "=f"(t12) : "l"(a01));
            asm("mov.b64 {%0,%1}, %2;" : "=f"(t21), "=f"(t22) : "l"(a23));
            if (jj == 3) { t11 += 1.f; t22 += 1.f; }     // + eye on true diagonal

            nmu = fmaf(t11, mu_j, fmaf(t12, ml_j, nmu));
            nml = fmaf(t21, mu_j, fmaf(t22, ml_j, nml));
            float cs2 = csj + csj;
            ncu = fmaf(t11 * t11, cuj, fmaf(t11 * t12, cs2, fmaf(t12 * t12, clj, ncu)));
            ncl = fmaf(t21 * t21, cuj, fmaf(t21 * t22, cs2, fmaf(t22 * t22, clj, ncl)));
            ncs = fmaf(t21 * t11, cuj,
                  fmaf(fmaf(t22, t11, t21 * t12), csj,
                  fmaf(t22 * t12, clj, ncs)));
        }
        // control MLP output for channels i and 60+i
        float ctl_u = s_bc2[i], ctl_l = s_bc2[LOD + i];
        #pragma unroll 4
        for (int m = 0; m < HH; m++) {
            float hm = s_h[m * PAD + lane];
            float2 w = s_wc2p[i * HH + m];
            ctl_u = fmaf(w.x, hm, ctl_u);
            ctl_l = fmaf(w.y, hm, ctl_l);
        }
        r_nmu[r] = nmu + ctl_u;
        r_nml[r] = nml + ctl_l;
        r_ncu[r] = ncu + s_tc[i];
        r_ncl[r] = ncl + s_tc[LOD + i];
        r_ncs[r] = ncs;
    }

    __syncthreads();                // all reads of s_mu..s_cs done
    float* s_out = s_mu;            // reuse 9900-float input region: [c(0..299)][lane]
    #pragma unroll
    for (int r = 0; r < RPT; r++) {
        int i = y + YD * r;
        s_out[(i)        * PAD + lane] = r_nmu[r];
        s_out[(LOD + i)  * PAD + lane] = r_nml[r];
        s_out[(120 + i)  * PAD + lane] = r_ncu[r];
        s_out[(180 + i)  * PAD + lane] = r_ncl[r];
        s_out[(240 + i)  * PAD + lane] = r_ncs[r];
    }
    __syncthreads();

    // coalesced global stores
    for (int e = tid; e < BT * 300; e += NT) {
        int bl = e / 300, c = e % 300;
        float v = s_out[c * PAD + bl];
        int b = b0 + bl;
        if (c < 120)      out[b * 120 + c] = v;
        else if (c < 180) out[NB_B * 120 + b * 60 + (c - 120)] = v;
        else if (c < 240) out[NB_B * 180 + b * 60 + (c - 180)] = v;
        else              out[NB_B * 240 + b * 60 + (c - 240)] = v;
    }
}

extern "C" void kernel_launch(void* const* d_in, const int* in_sizes, int n_in,
                              void* d_out, int out_size) {
    const float* post_mean = (const float*)d_in[0];
    const float* cu        = (const float*)d_in[1];
    const float* cl        = (const float*)d_in[2];
    const float* cs        = (const float*)d_in[3];
    const float* action    = (const float*)d_in[4];
    const float* tm11      = (const float*)d_in[5];
    const float* tm12      = (const float*)d_in[6];
    const float* tm21      = (const float*)d_in[7];
    const float* tm22      = (const float*)d_in[8];
    const float* log_noise = (const float*)d_in[9];
    const float* w_coef    = (const float*)d_in[10];
    const float* b_coef    = (const float*)d_in[11];
    const float* w_c1      = (const float*)d_in[12];
    const float* b_c1      = (const float*)d_in[13];
    const float* w_c2      = (const float*)d_in[14];
    const float* b_c2      = (const float*)d_in[15];
    float* out = (float*)d_out;

    pack_tmb_kernel<<<(LOD * 7 * NB + 255) / 256, 256>>>(tm11, tm12, tm21, tm22);

    const size_t smem = SMEM_FLOATS * sizeof(float);   // ~191 KB
    cudaFuncSetAttribute(acpredict_kernel,
                         cudaFuncAttributeMaxDynamicSharedMemorySize, (int)smem);
    dim3 blk(BT, YD);
    acpredict_kernel<<<NB_B / BT, blk, smem>>>(post_mean, cu, cl, cs, action,
                                               log_noise, w_coef, b_coef,
                                               w_c1, b_c1, w_c2, b_c2, out);
}